// round 6
// baseline (speedup 1.0000x reference)
#include <cuda_runtime.h>

// HarmonicOscillator. Reference cumsum = XLA ReduceWindowRewriter(base=16):
//   reshape [L/16, 16]; within-tile scan = SERIAL left fold (init 0)  [R5: HS falsified];
//   tile sums scanned recursively (16384 -> 1024 -> 64 -> 4, serial tiles);
//   combine: out = fl(outer_excl[r] + inner), row 0 exact.
// v = f0_up * fl32(1/22050)  (divide strength-reduced to reciprocal multiply;
//   R4's 0.0111 residual == eta*S drift with eta ~ 2.2e-8 = reciprocal rounding).
// Interp: two muls + add, no FMA contraction.

#define BATCH 8
#define FRAMES 512
#define NH 64
#define NS 262144              // 512*512
#define B16 16
#define ROWS (NS / B16)        // 16384

__device__ float g_P0[BATCH][NS];     // within-tile serial prefixes
__device__ float g_A1[BATCH][ROWS];   // tile sums -> in-place recursive scan

__device__ __forceinline__ float interp_c() {
    return (float)(511.0 / 262143.0);
}

__device__ __forceinline__ float compute_v(const float* __restrict__ fr, int n) {
    float nf  = (float)n;
    float pos = __fmul_rn(nf, interp_c());
    float fi0 = floorf(pos);
    int   i0  = (int)fi0;
    int   i1  = min(i0 + 1, FRAMES - 1);
    float w   = __fadd_rn(pos, -fi0);
    float omw = __fadd_rn(1.0f, -w);
    float up  = __fadd_rn(__fmul_rn(__ldg(fr + i0), omw), __fmul_rn(__ldg(fr + i1), w));
    const float RECIP_SR = (float)(1.0 / 22050.0);   // f32(1/22050)
    return __fmul_rn(up, RECIP_SR);
}

// ---------------- k1: per-tile serial prefixes + tile sums ----------------
__global__ void k1(const float* __restrict__ f0) {
    const int b = blockIdx.y;
    const int row = blockIdx.x * blockDim.x + threadIdx.x;   // 0..ROWS-1
    const float* fr = f0 + b * FRAMES;
    const int base = row * B16;
    float acc = 0.0f;
    #pragma unroll
    for (int c = 0; c < B16; ++c) {
        acc = __fadd_rn(acc, compute_v(fr, base + c));   // c=0: fl(0+v)=v
        g_P0[b][base + c] = acc;
    }
    g_A1[b][row] = acc;
}

// ---------------- recursive base-16 serial scan (in place) ----------------
template<int L>
__device__ void hc_scan(float* a, float* tmp, int t, int nt) {
    if constexpr (L <= B16) {
        if (t == 0) {
            float acc = 0.0f;
            #pragma unroll
            for (int i = 0; i < L; ++i) { acc = __fadd_rn(acc, a[i]); a[i] = acc; }
        }
        __syncthreads();
    } else {
        constexpr int R = L / B16;
        for (int r = t; r < R; r += nt) {
            float acc = 0.0f;
            #pragma unroll
            for (int c = 0; c < B16; ++c) {
                acc = __fadd_rn(acc, a[r * B16 + c]);
                a[r * B16 + c] = acc;
            }
            tmp[r] = acc;
        }
        __syncthreads();
        hc_scan<R>(tmp, tmp + R, t, nt);
        for (int j = t; j < L; j += nt) {
            int r = j >> 4;
            if (r > 0) a[j] = __fadd_rn(tmp[r - 1], a[j]);   // row 0 exact
        }
        __syncthreads();
    }
}

__global__ void k2() {
    const int b = blockIdx.x;
    __shared__ float stmp[1100];                   // 1024 + 64 + 4
    hc_scan<ROWS>(g_A1[b], stmp, threadIdx.x, blockDim.x);
}

// ---------------- sin of exact f32 argument (~5e-7 abs) ----------------
__device__ __forceinline__ float sin_match(float x) {
    const float INV2PI = (float)(1.0 / 6.283185307179586);
    const float C1 = 6.283185482025146484375f;     // f32(2pi)
    const float C2 = -1.7484556e-7f;               // residual
    float kf = rintf(__fmul_rn(x, INV2PI));
    float r  = fmaf(kf, -C1, x);
    r        = fmaf(kf, -C2, r);
    return __sinf(r);
}

// ---------------- main synthesis ----------------
__global__ void k_main(const float* __restrict__ amps, float* __restrict__ out) {
    const int b = blockIdx.y;
    const int n = blockIdx.x * 256 + threadIdx.x;

    const int r = n >> 4;
    float prev = (r > 0) ? g_A1[b][r - 1] : 0.0f;
    float S = __fadd_rn(prev, g_P0[b][n]);

    const float TWO_PI_F = 6.283185307179586f;
    float phase = __fmul_rn(S, TWO_PI_F);

    float nf  = (float)n;
    float pos = __fmul_rn(nf, interp_c());
    float fi0 = floorf(pos);
    int   i0  = (int)fi0;
    int   i1  = min(i0 + 1, FRAMES - 1);
    float w   = __fadd_rn(pos, -fi0);

    const float4* a0p = (const float4*)(amps + ((size_t)b * FRAMES + i0) * NH);
    const float4* a1p = (const float4*)(amps + ((size_t)b * FRAMES + i1) * NH);

    float acc0 = 0.0f, acc1 = 0.0f;
    #pragma unroll 4
    for (int q = 0; q < NH / 4; ++q) {
        float4 a0 = __ldg(a0p + q);
        float4 a1 = __ldg(a1p + q);
        float hb = (float)(4 * q + 1);

        float amp, pr;
        amp = fmaf(w, a1.x - a0.x, a0.x);
        pr  = __fmul_rn(phase, hb);
        acc0 = fmaf(sin_match(pr), amp, acc0);

        amp = fmaf(w, a1.y - a0.y, a0.y);
        pr  = __fmul_rn(phase, hb + 1.0f);
        acc1 = fmaf(sin_match(pr), amp, acc1);

        amp = fmaf(w, a1.z - a0.z, a0.z);
        pr  = __fmul_rn(phase, hb + 2.0f);
        acc0 = fmaf(sin_match(pr), amp, acc0);

        amp = fmaf(w, a1.w - a0.w, a0.w);
        pr  = __fmul_rn(phase, hb + 3.0f);
        acc1 = fmaf(sin_match(pr), amp, acc1);
    }
    out[(size_t)b * NS + n] = acc0 + acc1;
}

extern "C" void kernel_launch(void* const* d_in, const int* in_sizes, int n_in,
                              void* d_out, int out_size) {
    const float* f0   = (const float*)d_in[0];   // (8, 512)
    const float* amps = (const float*)d_in[1];   // (8, 512, 64)
    float* out = (float*)d_out;                  // (8, 262144)

    k1<<<dim3(ROWS / 512, BATCH), 512>>>(f0);
    k2<<<BATCH, 1024>>>();
    k_main<<<dim3(NS / 256, BATCH), 256>>>(amps, out);
}

// round 7
// speedup vs baseline: 1.4954x; 1.4954x over previous
#include <cuda_runtime.h>

// HarmonicOscillator — confirmed numerics (R6 pass, rel_err 2.7e-7):
//   v = f0_up * fl32(1/22050); interp = two muls + add (no contraction);
//   cumsum = XLA ReduceWindowRewriter(base=16), serial 16-folds per tile,
//   recursive levels 262144->16384->1024->64->4 (terminal serial), combine
//   out = fl(outer_excl + inner), row 0 exact.
// This round: packed f32x2 math in k_main, parallel scan pipeline, smem f0.

#define BATCH 8
#define FRAMES 512
#define NH 64
#define NS 262144              // 512*512
#define ROWS 16384             // NS/16

__device__ float g_P0[BATCH][NS];     // level-0 within-tile serial prefixes
__device__ float g_P1[BATCH][ROWS];   // level-1 within-tile prefixes
__device__ float g_T2[BATCH][1024];   // level-1 tile sums
__device__ float g_S1[BATCH][ROWS];   // full scan of tile sums (scan1)

typedef unsigned long long u64;

__device__ __forceinline__ u64 pk(float lo, float hi) {
    u64 r; asm("mov.b64 %0,{%1,%2};" : "=l"(r) : "f"(lo), "f"(hi)); return r;
}
__device__ __forceinline__ void upk(u64 v, float& lo, float& hi) {
    asm("mov.b64 {%0,%1},%2;" : "=f"(lo), "=f"(hi) : "l"(v));
}
__device__ __forceinline__ u64 fma2(u64 a, u64 b, u64 c) {
    u64 d; asm("fma.rn.f32x2 %0,%1,%2,%3;" : "=l"(d) : "l"(a), "l"(b), "l"(c)); return d;
}
__device__ __forceinline__ u64 mul2(u64 a, u64 b) {
    u64 d; asm("mul.rn.f32x2 %0,%1,%2;" : "=l"(d) : "l"(a), "l"(b)); return d;
}
__device__ __forceinline__ u64 add2(u64 a, u64 b) {
    u64 d; asm("add.rn.f32x2 %0,%1,%2;" : "=l"(d) : "l"(a), "l"(b)); return d;
}
__device__ __forceinline__ u64 sub2(u64 a, u64 b) {
    u64 d; asm("sub.rn.f32x2 %0,%1,%2;" : "=l"(d) : "l"(a), "l"(b)); return d;
}

__device__ __forceinline__ float interp_c() {
    return (float)(511.0 / 262143.0);
}

__device__ __forceinline__ float compute_v(const float* __restrict__ sf0, int n) {
    float nf  = (float)n;
    float pos = __fmul_rn(nf, interp_c());
    float fi0 = floorf(pos);
    int   i0  = (int)fi0;
    int   i1  = min(i0 + 1, FRAMES - 1);
    float w   = __fadd_rn(pos, -fi0);
    float omw = __fadd_rn(1.0f, -w);
    float up  = __fadd_rn(__fmul_rn(sf0[i0], omw), __fmul_rn(sf0[i1], w));
    const float RECIP_SR = (float)(1.0 / 22050.0);
    return __fmul_rn(up, RECIP_SR);
}

// ---- k1: level-0 prefixes P0 + local level-1 prefixes P1 + tile sums T2 ----
__global__ void k1(const float* __restrict__ f0) {
    const int b = blockIdx.y;
    const int t = threadIdx.x;                  // 0..511
    const int row = blockIdx.x * 512 + t;       // global tile index

    __shared__ float sf0[FRAMES];
    __shared__ float sT1[512];
    __shared__ float sP1[512];
    sf0[t] = f0[b * FRAMES + t];
    __syncthreads();

    const int base = row * 16;
    float x[16];
    float acc = 0.0f;
    #pragma unroll
    for (int c = 0; c < 16; ++c) {
        acc = __fadd_rn(acc, compute_v(sf0, base + c));
        x[c] = acc;
    }
    float4* dst = (float4*)(g_P0[b] + base);
    dst[0] = make_float4(x[0],  x[1],  x[2],  x[3]);
    dst[1] = make_float4(x[4],  x[5],  x[6],  x[7]);
    dst[2] = make_float4(x[8],  x[9],  x[10], x[11]);
    dst[3] = make_float4(x[12], x[13], x[14], x[15]);

    sT1[t] = acc;
    __syncthreads();
    if (t < 32) {
        float a2 = 0.0f;
        #pragma unroll
        for (int c = 0; c < 16; ++c) {
            a2 = __fadd_rn(a2, sT1[t * 16 + c]);
            sP1[t * 16 + c] = a2;
        }
        g_T2[b][blockIdx.x * 32 + t] = a2;
    }
    __syncthreads();
    g_P1[b][row] = sP1[t];
}

// ---- k2: levels 2..4 in smem, emit full scan1 ----
__global__ void k2() {
    const int b = blockIdx.x;
    const int t = threadIdx.x;                  // 0..1023
    __shared__ float sP2[1024];
    __shared__ float sS3[64];
    __shared__ float sP4[4];

    if (t < 64) {                               // P2: 64 serial folds of 16
        float a = 0.0f;
        #pragma unroll
        for (int c = 0; c < 16; ++c) {
            a = __fadd_rn(a, g_T2[b][t * 16 + c]);
            sP2[t * 16 + c] = a;
        }
    }
    __syncthreads();
    if (t < 4) {                                // P3 over T3 = sP2[m*16+15]
        float a = 0.0f;
        #pragma unroll
        for (int c = 0; c < 16; ++c) {
            a = __fadd_rn(a, sP2[(t * 16 + c) * 16 + 15]);
            sS3[t * 16 + c] = a;
        }
    }
    __syncthreads();
    if (t == 0) {                               // P4 over T4 (terminal serial)
        float a = 0.0f;
        #pragma unroll
        for (int c = 0; c < 4; ++c) {
            a = __fadd_rn(a, sS3[c * 16 + 15]);
            sP4[c] = a;
        }
    }
    __syncthreads();
    if (t < 48) {                               // scan3 in place (m >= 16)
        int m = t + 16;
        sS3[m] = __fadd_rn(sP4[(m >> 4) - 1], sS3[m]);
    }
    __syncthreads();
    if (t >= 16)                                // scan2 in place
        sP2[t] = __fadd_rn(sS3[(t >> 4) - 1], sP2[t]);
    __syncthreads();
    #pragma unroll
    for (int k = 0; k < 16; ++k) {              // scan1 -> g_S1
        int j = t + k * 1024;
        float p1 = g_P1[b][j];
        g_S1[b][j] = (j < 16) ? p1 : __fadd_rn(sP2[(j >> 4) - 1], p1);
    }
}

// ---- k_main: packed f32x2 synthesis ----
__global__ void k_main(const float* __restrict__ amps, float* __restrict__ out) {
    const int b = blockIdx.y;
    const int n = blockIdx.x * 256 + threadIdx.x;

    const int r0 = n >> 4;
    float prev = (r0 > 0) ? g_S1[b][r0 - 1] : 0.0f;
    float S = __fadd_rn(prev, g_P0[b][n]);
    const float TWO_PI_F = 6.283185307179586f;
    float phase = __fmul_rn(S, TWO_PI_F);

    float nf  = (float)n;
    float pos = __fmul_rn(nf, interp_c());
    float fi0 = floorf(pos);
    int   i0  = (int)fi0;
    int   i1  = min(i0 + 1, FRAMES - 1);
    float w   = __fadd_rn(pos, -fi0);

    const ulonglong2* __restrict__ a0p =
        (const ulonglong2*)(amps + ((size_t)b * FRAMES + i0) * NH);
    const ulonglong2* __restrict__ a1p =
        (const ulonglong2*)(amps + ((size_t)b * FRAMES + i1) * NH);

    const float INV2PI = (float)(1.0 / 6.283185307179586);
    const float C1 = 6.283185482025146484375f;
    const float C2 = -1.7484556e-7f;
    const float MAGIC = 12582912.0f;            // 1.5 * 2^23

    u64 w2   = pk(w, w);
    u64 ph2  = pk(phase, phase);
    u64 IV2  = pk(INV2PI, INV2PI);
    u64 MG2  = pk(MAGIC, MAGIC);
    u64 C1n  = pk(-C1, -C1);
    u64 C2n  = pk(-C2, -C2);
    u64 FOUR = pk(4.0f, 4.0f);
    u64 h2a  = pk(1.0f, 2.0f);
    u64 h2b  = pk(3.0f, 4.0f);
    u64 acc  = pk(0.0f, 0.0f);

    #pragma unroll
    for (int q = 0; q < NH / 4; ++q) {
        ulonglong2 A0 = a0p[q];
        ulonglong2 A1 = a1p[q];

        // pair a: harmonics (4q+1, 4q+2)
        {
            u64 amp = fma2(w2, sub2(A1.x, A0.x), A0.x);
            u64 pr  = mul2(ph2, h2a);
            u64 tt  = fma2(pr, IV2, MG2);
            u64 kf  = sub2(tt, MG2);
            u64 r   = fma2(kf, C1n, pr);
            r       = fma2(kf, C2n, r);
            float rl, rh; upk(r, rl, rh);
            u64 s2  = pk(__sinf(rl), __sinf(rh));
            acc     = fma2(s2, amp, acc);
        }
        // pair b: harmonics (4q+3, 4q+4)
        {
            u64 amp = fma2(w2, sub2(A1.y, A0.y), A0.y);
            u64 pr  = mul2(ph2, h2b);
            u64 tt  = fma2(pr, IV2, MG2);
            u64 kf  = sub2(tt, MG2);
            u64 r   = fma2(kf, C1n, pr);
            r       = fma2(kf, C2n, r);
            float rl, rh; upk(r, rl, rh);
            u64 s2  = pk(__sinf(rl), __sinf(rh));
            acc     = fma2(s2, amp, acc);
        }
        h2a = add2(h2a, FOUR);
        h2b = add2(h2b, FOUR);
    }
    float al, ah; upk(acc, al, ah);
    out[(size_t)b * NS + n] = __fadd_rn(al, ah);
}

extern "C" void kernel_launch(void* const* d_in, const int* in_sizes, int n_in,
                              void* d_out, int out_size) {
    const float* f0   = (const float*)d_in[0];   // (8, 512)
    const float* amps = (const float*)d_in[1];   // (8, 512, 64)
    float* out = (float*)d_out;                  // (8, 262144)

    k1<<<dim3(ROWS / 512, BATCH), 512>>>(f0);
    k2<<<BATCH, 1024>>>();
    k_main<<<dim3(NS / 256, BATCH), 256>>>(amps, out);
}

// round 8
// speedup vs baseline: 1.6524x; 1.1050x over previous
#include <cuda_runtime.h>

// HarmonicOscillator — confirmed numerics (R6/R7 pass, rel_err 2.7e-7):
//   v = f0_up * fl32(1/22050); interp = two muls + add (no contraction);
//   cumsum = XLA ReduceWindowRewriter(base=16), serial 16-folds per tile,
//   levels 262144->16384->1024->64->4 (terminal serial), combine
//   out = fl(outer_excl + inner), row 0 exact.
// R8: k_main reconstructs S from (scan2, P1, P0) with identical fl nesting;
//     two packed accumulators + compile-time harmonic constants; k2 tiny.

#define BATCH 8
#define FRAMES 512
#define NH 64
#define NS 262144              // 512*512
#define ROWS 16384             // NS/16

__device__ float g_P0[BATCH][NS];     // level-0 within-tile serial prefixes
__device__ float g_P1[BATCH][ROWS];   // level-1 within-tile prefixes
__device__ float g_T2[BATCH][1024];   // level-1 tile sums
__device__ float g_S2[BATCH][1024];   // full scan of level-2 (scan2)

typedef unsigned long long u64;

__device__ __forceinline__ u64 pk(float lo, float hi) {
    u64 r; asm("mov.b64 %0,{%1,%2};" : "=l"(r) : "f"(lo), "f"(hi)); return r;
}
__device__ __forceinline__ void upk(u64 v, float& lo, float& hi) {
    asm("mov.b64 {%0,%1},%2;" : "=f"(lo), "=f"(hi) : "l"(v));
}
__device__ __forceinline__ u64 fma2(u64 a, u64 b, u64 c) {
    u64 d; asm("fma.rn.f32x2 %0,%1,%2,%3;" : "=l"(d) : "l"(a), "l"(b), "l"(c)); return d;
}
__device__ __forceinline__ u64 mul2(u64 a, u64 b) {
    u64 d; asm("mul.rn.f32x2 %0,%1,%2;" : "=l"(d) : "l"(a), "l"(b)); return d;
}
__device__ __forceinline__ u64 sub2(u64 a, u64 b) {
    u64 d; asm("sub.rn.f32x2 %0,%1,%2;" : "=l"(d) : "l"(a), "l"(b)); return d;
}

__device__ __forceinline__ float interp_c() {
    return (float)(511.0 / 262143.0);
}

__device__ __forceinline__ float compute_v(const float* __restrict__ sf0, int n) {
    float nf  = (float)n;
    float pos = __fmul_rn(nf, interp_c());
    float fi0 = floorf(pos);
    int   i0  = (int)fi0;
    int   i1  = min(i0 + 1, FRAMES - 1);
    float w   = __fadd_rn(pos, -fi0);
    float omw = __fadd_rn(1.0f, -w);
    float up  = __fadd_rn(__fmul_rn(sf0[i0], omw), __fmul_rn(sf0[i1], w));
    const float RECIP_SR = (float)(1.0 / 22050.0);
    return __fmul_rn(up, RECIP_SR);
}

// ---- k1: P0 tile prefixes + P1 level-1 prefixes + T2 tile sums ----
// 256 threads/block, 256 tiles/block, grid (64, BATCH)
__global__ void k1(const float* __restrict__ f0) {
    const int b = blockIdx.y;
    const int t = threadIdx.x;                  // 0..255
    const int row = blockIdx.x * 256 + t;

    __shared__ float sf0[FRAMES];
    __shared__ float sT1[256];
    __shared__ float sP1[256];
    sf0[t] = f0[b * FRAMES + t];
    sf0[t + 256] = f0[b * FRAMES + t + 256];
    __syncthreads();

    const int base = row * 16;
    float x[16];
    float acc = 0.0f;
    #pragma unroll
    for (int c = 0; c < 16; ++c) {
        acc = __fadd_rn(acc, compute_v(sf0, base + c));
        x[c] = acc;
    }
    float4* dst = (float4*)(g_P0[b] + base);
    dst[0] = make_float4(x[0],  x[1],  x[2],  x[3]);
    dst[1] = make_float4(x[4],  x[5],  x[6],  x[7]);
    dst[2] = make_float4(x[8],  x[9],  x[10], x[11]);
    dst[3] = make_float4(x[12], x[13], x[14], x[15]);

    sT1[t] = acc;
    __syncthreads();
    if (t < 16) {
        float a2 = 0.0f;
        #pragma unroll
        for (int c = 0; c < 16; ++c) {
            a2 = __fadd_rn(a2, sT1[t * 16 + c]);
            sP1[t * 16 + c] = a2;
        }
        g_T2[b][blockIdx.x * 16 + t] = a2;
    }
    __syncthreads();
    g_P1[b][row] = sP1[t];
}

// ---- k2: levels 2..4, emit scan2 (1024/batch) ----
__global__ void k2() {
    const int b = blockIdx.x;
    const int t = threadIdx.x;                  // 0..127
    __shared__ float sP2[1024];
    __shared__ float sS3[64];
    __shared__ float sP4[4];

    if (t < 64) {                               // P2: 64 serial folds of 16
        float a = 0.0f;
        #pragma unroll
        for (int c = 0; c < 16; ++c) {
            a = __fadd_rn(a, g_T2[b][t * 16 + c]);
            sP2[t * 16 + c] = a;
        }
    }
    __syncthreads();
    if (t < 4) {                                // P3 over T3
        float a = 0.0f;
        #pragma unroll
        for (int c = 0; c < 16; ++c) {
            a = __fadd_rn(a, sP2[(t * 16 + c) * 16 + 15]);
            sS3[t * 16 + c] = a;
        }
    }
    __syncthreads();
    if (t == 0) {                               // P4 (terminal serial)
        float a = 0.0f;
        #pragma unroll
        for (int c = 0; c < 4; ++c) {
            a = __fadd_rn(a, sS3[c * 16 + 15]);
            sP4[c] = a;
        }
    }
    __syncthreads();
    if (t < 48) {                               // scan3 in place (m >= 16)
        int m = t + 16;
        sS3[m] = __fadd_rn(sP4[(m >> 4) - 1], sS3[m]);
    }
    __syncthreads();
    #pragma unroll
    for (int k = 0; k < 8; ++k) {               // scan2 -> g_S2
        int j = t + k * 128;
        float p2 = sP2[j];
        g_S2[b][j] = (j < 16) ? p2 : __fadd_rn(sS3[(j >> 4) - 1], p2);
    }
}

// ---- k_main: packed f32x2 synthesis ----
__global__ void __launch_bounds__(256) k_main(const float* __restrict__ amps,
                                              float* __restrict__ out) {
    const int b = blockIdx.y;
    const int n = blockIdx.x * 256 + threadIdx.x;

    // S with exact reference fl nesting: scan1[j] = fl(scan2[j>>4 -1] + P1[j])
    float p0 = g_P0[b][n];
    const int r1 = n >> 4;
    float S;
    if (r1 == 0) {
        S = p0;
    } else {
        const int j = r1 - 1;
        float p1 = g_P1[b][j];
        const int r2 = j >> 4;
        float s1 = (r2 == 0) ? p1 : __fadd_rn(g_S2[b][r2 - 1], p1);
        S = __fadd_rn(s1, p0);
    }
    const float TWO_PI_F = 6.283185307179586f;
    float phase = __fmul_rn(S, TWO_PI_F);

    float nf  = (float)n;
    float pos = __fmul_rn(nf, interp_c());
    float fi0 = floorf(pos);
    int   i0  = (int)fi0;
    int   i1  = min(i0 + 1, FRAMES - 1);
    float w   = __fadd_rn(pos, -fi0);

    const ulonglong2* __restrict__ a0p =
        (const ulonglong2*)(amps + ((size_t)b * FRAMES + i0) * NH);
    const ulonglong2* __restrict__ a1p =
        (const ulonglong2*)(amps + ((size_t)b * FRAMES + i1) * NH);

    const float INV2PI = (float)(1.0 / 6.283185307179586);
    const float C1 = 6.283185482025146484375f;
    const float C2 = -1.7484556e-7f;
    const float MAGIC = 12582912.0f;            // 1.5 * 2^23

    u64 w2  = pk(w, w);
    u64 ph2 = pk(phase, phase);
    u64 IV2 = pk(INV2PI, INV2PI);
    u64 MG2 = pk(MAGIC, MAGIC);
    u64 C1n = pk(-C1, -C1);
    u64 C2n = pk(-C2, -C2);
    u64 accA = pk(0.0f, 0.0f);
    u64 accB = pk(0.0f, 0.0f);

    #pragma unroll
    for (int q = 0; q < NH / 4; ++q) {
        ulonglong2 A0 = a0p[q];
        ulonglong2 A1 = a1p[q];
        // compile-time harmonic constants (no recurrence)
        u64 hA = pk((float)(4 * q + 1), (float)(4 * q + 2));
        u64 hB = pk((float)(4 * q + 3), (float)(4 * q + 4));

        {   // harmonics 4q+1, 4q+2 -> accA
            u64 amp = fma2(w2, sub2(A1.x, A0.x), A0.x);
            u64 pr  = mul2(ph2, hA);
            u64 tt  = fma2(pr, IV2, MG2);
            u64 kf  = sub2(tt, MG2);
            u64 r   = fma2(kf, C1n, pr);
            r       = fma2(kf, C2n, r);
            float rl, rh; upk(r, rl, rh);
            u64 s2  = pk(__sinf(rl), __sinf(rh));
            accA    = fma2(s2, amp, accA);
        }
        {   // harmonics 4q+3, 4q+4 -> accB
            u64 amp = fma2(w2, sub2(A1.y, A0.y), A0.y);
            u64 pr  = mul2(ph2, hB);
            u64 tt  = fma2(pr, IV2, MG2);
            u64 kf  = sub2(tt, MG2);
            u64 r   = fma2(kf, C1n, pr);
            r       = fma2(kf, C2n, r);
            float rl, rh; upk(r, rl, rh);
            u64 s2  = pk(__sinf(rl), __sinf(rh));
            accB    = fma2(s2, amp, accB);
        }
    }
    float al, ah, bl, bh;
    upk(accA, al, ah);
    upk(accB, bl, bh);
    out[(size_t)b * NS + n] = (al + ah) + (bl + bh);
}

extern "C" void kernel_launch(void* const* d_in, const int* in_sizes, int n_in,
                              void* d_out, int out_size) {
    const float* f0   = (const float*)d_in[0];   // (8, 512)
    const float* amps = (const float*)d_in[1];   // (8, 512, 64)
    float* out = (float*)d_out;                  // (8, 262144)

    k1<<<dim3(ROWS / 256, BATCH), 256>>>(f0);
    k2<<<BATCH, 128>>>();
    k_main<<<dim3(NS / 256, BATCH), 256>>>(amps, out);
}

// round 9
// speedup vs baseline: 1.7837x; 1.0795x over previous
#include <cuda_runtime.h>

// HarmonicOscillator — confirmed numerics (rel_err 2.6e-7):
//   v = f0_up * fl32(1/22050); interp = two muls + add (no contraction);
//   cumsum = XLA ReduceWindowRewriter(base=16), serial 16-folds per tile,
//   levels 262144->16384->1024->64->4 (terminal serial), combine
//   out = fl(outer_excl + inner), row 0 exact.
// R9: per-block smem staging of amp rows A0 / DIFF (removes sub2 from the
//     hot loop: 16 -> 14 FMA-pipe ops per 4 harmonics).

#define BATCH 8
#define FRAMES 512
#define NH 64
#define NS 262144              // 512*512
#define ROWS 16384             // NS/16

__device__ float g_P0[BATCH][NS];     // level-0 within-tile serial prefixes
__device__ float g_P1[BATCH][ROWS];   // level-1 within-tile prefixes
__device__ float g_T2[BATCH][1024];   // level-1 tile sums
__device__ float g_S2[BATCH][1024];   // full scan of level-2 (scan2)

typedef unsigned long long u64;

__device__ __forceinline__ u64 pk(float lo, float hi) {
    u64 r; asm("mov.b64 %0,{%1,%2};" : "=l"(r) : "f"(lo), "f"(hi)); return r;
}
__device__ __forceinline__ void upk(u64 v, float& lo, float& hi) {
    asm("mov.b64 {%0,%1},%2;" : "=f"(lo), "=f"(hi) : "l"(v));
}
__device__ __forceinline__ u64 fma2(u64 a, u64 b, u64 c) {
    u64 d; asm("fma.rn.f32x2 %0,%1,%2,%3;" : "=l"(d) : "l"(a), "l"(b), "l"(c)); return d;
}
__device__ __forceinline__ u64 mul2(u64 a, u64 b) {
    u64 d; asm("mul.rn.f32x2 %0,%1,%2;" : "=l"(d) : "l"(a), "l"(b)); return d;
}
__device__ __forceinline__ u64 sub2(u64 a, u64 b) {
    u64 d; asm("sub.rn.f32x2 %0,%1,%2;" : "=l"(d) : "l"(a), "l"(b)); return d;
}

__device__ __forceinline__ float interp_c() {
    return (float)(511.0 / 262143.0);
}

__device__ __forceinline__ float compute_v(const float* __restrict__ sf0, int n) {
    float nf  = (float)n;
    float pos = __fmul_rn(nf, interp_c());
    float fi0 = floorf(pos);
    int   i0  = (int)fi0;
    int   i1  = min(i0 + 1, FRAMES - 1);
    float w   = __fadd_rn(pos, -fi0);
    float omw = __fadd_rn(1.0f, -w);
    float up  = __fadd_rn(__fmul_rn(sf0[i0], omw), __fmul_rn(sf0[i1], w));
    const float RECIP_SR = (float)(1.0 / 22050.0);
    return __fmul_rn(up, RECIP_SR);
}

// ---- k1: P0 tile prefixes + P1 level-1 prefixes + T2 tile sums ----
__global__ void k1(const float* __restrict__ f0) {
    const int b = blockIdx.y;
    const int t = threadIdx.x;                  // 0..255
    const int row = blockIdx.x * 256 + t;

    __shared__ float sf0[FRAMES];
    __shared__ float sT1[256];
    __shared__ float sP1[256];
    sf0[t] = f0[b * FRAMES + t];
    sf0[t + 256] = f0[b * FRAMES + t + 256];
    __syncthreads();

    const int base = row * 16;
    float x[16];
    float acc = 0.0f;
    #pragma unroll
    for (int c = 0; c < 16; ++c) {
        acc = __fadd_rn(acc, compute_v(sf0, base + c));
        x[c] = acc;
    }
    float4* dst = (float4*)(g_P0[b] + base);
    dst[0] = make_float4(x[0],  x[1],  x[2],  x[3]);
    dst[1] = make_float4(x[4],  x[5],  x[6],  x[7]);
    dst[2] = make_float4(x[8],  x[9],  x[10], x[11]);
    dst[3] = make_float4(x[12], x[13], x[14], x[15]);

    sT1[t] = acc;
    __syncthreads();
    if (t < 16) {
        float a2 = 0.0f;
        #pragma unroll
        for (int c = 0; c < 16; ++c) {
            a2 = __fadd_rn(a2, sT1[t * 16 + c]);
            sP1[t * 16 + c] = a2;
        }
        g_T2[b][blockIdx.x * 16 + t] = a2;
    }
    __syncthreads();
    g_P1[b][row] = sP1[t];
}

// ---- k2: levels 2..4, emit scan2 (1024/batch) ----
__global__ void k2() {
    const int b = blockIdx.x;
    const int t = threadIdx.x;                  // 0..127
    __shared__ float sP2[1024];
    __shared__ float sS3[64];
    __shared__ float sP4[4];

    if (t < 64) {
        float a = 0.0f;
        #pragma unroll
        for (int c = 0; c < 16; ++c) {
            a = __fadd_rn(a, g_T2[b][t * 16 + c]);
            sP2[t * 16 + c] = a;
        }
    }
    __syncthreads();
    if (t < 4) {
        float a = 0.0f;
        #pragma unroll
        for (int c = 0; c < 16; ++c) {
            a = __fadd_rn(a, sP2[(t * 16 + c) * 16 + 15]);
            sS3[t * 16 + c] = a;
        }
    }
    __syncthreads();
    if (t == 0) {
        float a = 0.0f;
        #pragma unroll
        for (int c = 0; c < 4; ++c) {
            a = __fadd_rn(a, sS3[c * 16 + 15]);
            sP4[c] = a;
        }
    }
    __syncthreads();
    if (t < 48) {
        int m = t + 16;
        sS3[m] = __fadd_rn(sP4[(m >> 4) - 1], sS3[m]);
    }
    __syncthreads();
    #pragma unroll
    for (int k = 0; k < 8; ++k) {
        int j = t + k * 128;
        float p2 = sP2[j];
        g_S2[b][j] = (j < 16) ? p2 : __fadd_rn(sS3[(j >> 4) - 1], p2);
    }
}

// ---- k_main: packed f32x2 synthesis with smem amp staging ----
__global__ void __launch_bounds__(256) k_main(const float* __restrict__ amps,
                                              float* __restrict__ out) {
    const int b = blockIdx.y;
    const int n0 = blockIdx.x * 256;
    const int t = threadIdx.x;
    const int n = n0 + t;

    // block-uniform first frame index (same formula as per-thread path)
    float posF = __fmul_rn((float)n0, interp_c());
    const int i0f = (int)floorf(posF);

    __shared__ u64 sA0[2][32];
    __shared__ u64 sDF[2][32];
    if (t < 64) {
        int g = t >> 5;                          // 0 or 1
        int s = t & 31;                          // u64 slot (2 floats)
        int r0 = min(i0f + g, FRAMES - 1);
        int r1 = min(r0 + 1, FRAMES - 1);
        const u64* rowA = (const u64*)(amps + ((size_t)b * FRAMES + r0) * NH);
        const u64* rowB = (const u64*)(amps + ((size_t)b * FRAMES + r1) * NH);
        u64 a0 = __ldg(rowA + s);
        u64 a1 = __ldg(rowB + s);
        sA0[g][s] = a0;
        sDF[g][s] = sub2(a1, a0);                // same per-lane fl sub as ref path
    }

    // S with exact reference fl nesting
    float p0 = g_P0[b][n];
    const int r1i = n >> 4;
    float S;
    if (r1i == 0) {
        S = p0;
    } else {
        const int j = r1i - 1;
        float p1 = g_P1[b][j];
        const int r2 = j >> 4;
        float s1 = (r2 == 0) ? p1 : __fadd_rn(g_S2[b][r2 - 1], p1);
        S = __fadd_rn(s1, p0);
    }
    const float TWO_PI_F = 6.283185307179586f;
    float phase = __fmul_rn(S, TWO_PI_F);

    float nf  = (float)n;
    float pos = __fmul_rn(nf, interp_c());
    float fi0 = floorf(pos);
    int   i0  = (int)fi0;
    float w   = __fadd_rn(pos, -fi0);
    const int g = i0 - i0f;                      // 0 or 1

    __syncthreads();

    const float INV2PI = (float)(1.0 / 6.283185307179586);
    const float C1 = 6.283185482025146484375f;
    const float C2 = -1.7484556e-7f;
    const float MAGIC = 12582912.0f;             // 1.5 * 2^23

    u64 w2  = pk(w, w);
    u64 ph2 = pk(phase, phase);
    u64 IV2 = pk(INV2PI, INV2PI);
    u64 MG2 = pk(MAGIC, MAGIC);
    u64 C1n = pk(-C1, -C1);
    u64 C2n = pk(-C2, -C2);
    u64 accA = pk(0.0f, 0.0f);
    u64 accB = pk(0.0f, 0.0f);

    #pragma unroll
    for (int q = 0; q < NH / 4; ++q) {
        u64 hA = pk((float)(4 * q + 1), (float)(4 * q + 2));
        u64 hB = pk((float)(4 * q + 3), (float)(4 * q + 4));

        {   // harmonics 4q+1, 4q+2 -> accA
            u64 amp = fma2(w2, sDF[g][2 * q], sA0[g][2 * q]);
            u64 pr  = mul2(ph2, hA);
            u64 tt  = fma2(pr, IV2, MG2);
            u64 kf  = sub2(tt, MG2);
            u64 r   = fma2(kf, C1n, pr);
            r       = fma2(kf, C2n, r);
            float rl, rh; upk(r, rl, rh);
            u64 s2  = pk(__sinf(rl), __sinf(rh));
            accA    = fma2(s2, amp, accA);
        }
        {   // harmonics 4q+3, 4q+4 -> accB
            u64 amp = fma2(w2, sDF[g][2 * q + 1], sA0[g][2 * q + 1]);
            u64 pr  = mul2(ph2, hB);
            u64 tt  = fma2(pr, IV2, MG2);
            u64 kf  = sub2(tt, MG2);
            u64 r   = fma2(kf, C1n, pr);
            r       = fma2(kf, C2n, r);
            float rl, rh; upk(r, rl, rh);
            u64 s2  = pk(__sinf(rl), __sinf(rh));
            accB    = fma2(s2, amp, accB);
        }
    }
    float al, ah, bl, bh;
    upk(accA, al, ah);
    upk(accB, bl, bh);
    out[(size_t)b * NS + n] = (al + ah) + (bl + bh);
}

extern "C" void kernel_launch(void* const* d_in, const int* in_sizes, int n_in,
                              void* d_out, int out_size) {
    const float* f0   = (const float*)d_in[0];   // (8, 512)
    const float* amps = (const float*)d_in[1];   // (8, 512, 64)
    float* out = (float*)d_out;                  // (8, 262144)

    k1<<<dim3(ROWS / 256, BATCH), 256>>>(f0);
    k2<<<BATCH, 128>>>();
    k_main<<<dim3(NS / 256, BATCH), 256>>>(amps, out);
}

// round 10
// speedup vs baseline: 1.7926x; 1.0050x over previous
#include <cuda_runtime.h>

// HarmonicOscillator — confirmed numerics (rel_err 2.6e-7):
//   v = f0_up * fl32(1/22050); interp = two muls + add (no contraction);
//   cumsum = XLA ReduceWindowRewriter(base=16), serial 16-folds per tile,
//   levels 262144->16384->1024->64->4 (terminal serial), combine
//   out = fl(outer_excl + inner), row 0 exact.
// R10: k_main processes 2 samples/thread (128 thr/block) -> 4 acc chains,
//      8 MUFU streams per unrolled iter, to close the ~10us latency gap.

#define BATCH 8
#define FRAMES 512
#define NH 64
#define NS 262144              // 512*512
#define ROWS 16384             // NS/16

__device__ float g_P0[BATCH][NS];
__device__ float g_P1[BATCH][ROWS];
__device__ float g_T2[BATCH][1024];
__device__ float g_S2[BATCH][1024];

typedef unsigned long long u64;

__device__ __forceinline__ u64 pk(float lo, float hi) {
    u64 r; asm("mov.b64 %0,{%1,%2};" : "=l"(r) : "f"(lo), "f"(hi)); return r;
}
__device__ __forceinline__ void upk(u64 v, float& lo, float& hi) {
    asm("mov.b64 {%0,%1},%2;" : "=f"(lo), "=f"(hi) : "l"(v));
}
__device__ __forceinline__ u64 fma2(u64 a, u64 b, u64 c) {
    u64 d; asm("fma.rn.f32x2 %0,%1,%2,%3;" : "=l"(d) : "l"(a), "l"(b), "l"(c)); return d;
}
__device__ __forceinline__ u64 mul2(u64 a, u64 b) {
    u64 d; asm("mul.rn.f32x2 %0,%1,%2;" : "=l"(d) : "l"(a), "l"(b)); return d;
}
__device__ __forceinline__ u64 sub2(u64 a, u64 b) {
    u64 d; asm("sub.rn.f32x2 %0,%1,%2;" : "=l"(d) : "l"(a), "l"(b)); return d;
}

__device__ __forceinline__ float interp_c() {
    return (float)(511.0 / 262143.0);
}

__device__ __forceinline__ float compute_v(const float* __restrict__ sf0, int n) {
    float nf  = (float)n;
    float pos = __fmul_rn(nf, interp_c());
    float fi0 = floorf(pos);
    int   i0  = (int)fi0;
    int   i1  = min(i0 + 1, FRAMES - 1);
    float w   = __fadd_rn(pos, -fi0);
    float omw = __fadd_rn(1.0f, -w);
    float up  = __fadd_rn(__fmul_rn(sf0[i0], omw), __fmul_rn(sf0[i1], w));
    const float RECIP_SR = (float)(1.0 / 22050.0);
    return __fmul_rn(up, RECIP_SR);
}

// ---- k1: P0 tile prefixes + P1 level-1 prefixes + T2 tile sums ----
__global__ void k1(const float* __restrict__ f0) {
    const int b = blockIdx.y;
    const int t = threadIdx.x;                  // 0..255
    const int row = blockIdx.x * 256 + t;

    __shared__ float sf0[FRAMES];
    __shared__ float sT1[256];
    __shared__ float sP1[256];
    sf0[t] = f0[b * FRAMES + t];
    sf0[t + 256] = f0[b * FRAMES + t + 256];
    __syncthreads();

    const int base = row * 16;
    float x[16];
    float acc = 0.0f;
    #pragma unroll
    for (int c = 0; c < 16; ++c) {
        acc = __fadd_rn(acc, compute_v(sf0, base + c));
        x[c] = acc;
    }
    float4* dst = (float4*)(g_P0[b] + base);
    dst[0] = make_float4(x[0],  x[1],  x[2],  x[3]);
    dst[1] = make_float4(x[4],  x[5],  x[6],  x[7]);
    dst[2] = make_float4(x[8],  x[9],  x[10], x[11]);
    dst[3] = make_float4(x[12], x[13], x[14], x[15]);

    sT1[t] = acc;
    __syncthreads();
    if (t < 16) {
        float a2 = 0.0f;
        #pragma unroll
        for (int c = 0; c < 16; ++c) {
            a2 = __fadd_rn(a2, sT1[t * 16 + c]);
            sP1[t * 16 + c] = a2;
        }
        g_T2[b][blockIdx.x * 16 + t] = a2;
    }
    __syncthreads();
    g_P1[b][row] = sP1[t];
}

// ---- k2: levels 2..4, emit scan2 (1024/batch) ----
__global__ void k2() {
    const int b = blockIdx.x;
    const int t = threadIdx.x;                  // 0..127
    __shared__ float sP2[1024];
    __shared__ float sS3[64];
    __shared__ float sP4[4];

    if (t < 64) {
        float a = 0.0f;
        #pragma unroll
        for (int c = 0; c < 16; ++c) {
            a = __fadd_rn(a, g_T2[b][t * 16 + c]);
            sP2[t * 16 + c] = a;
        }
    }
    __syncthreads();
    if (t < 4) {
        float a = 0.0f;
        #pragma unroll
        for (int c = 0; c < 16; ++c) {
            a = __fadd_rn(a, sP2[(t * 16 + c) * 16 + 15]);
            sS3[t * 16 + c] = a;
        }
    }
    __syncthreads();
    if (t == 0) {
        float a = 0.0f;
        #pragma unroll
        for (int c = 0; c < 4; ++c) {
            a = __fadd_rn(a, sS3[c * 16 + 15]);
            sP4[c] = a;
        }
    }
    __syncthreads();
    if (t < 48) {
        int m = t + 16;
        sS3[m] = __fadd_rn(sP4[(m >> 4) - 1], sS3[m]);
    }
    __syncthreads();
    #pragma unroll
    for (int k = 0; k < 8; ++k) {
        int j = t + k * 128;
        float p2 = sP2[j];
        g_S2[b][j] = (j < 16) ? p2 : __fadd_rn(sS3[(j >> 4) - 1], p2);
    }
}

// ---- S reconstruction (exact reference fl nesting) ----
__device__ __forceinline__ float recon_S(int b, int n) {
    float p0 = g_P0[b][n];
    const int r1i = n >> 4;
    if (r1i == 0) return p0;
    const int j = r1i - 1;
    float p1 = g_P1[b][j];
    const int r2 = j >> 4;
    float s1 = (r2 == 0) ? p1 : __fadd_rn(g_S2[b][r2 - 1], p1);
    return __fadd_rn(s1, p0);
}

// ---- k_main: packed f32x2 synthesis, 2 samples/thread ----
__global__ void __launch_bounds__(128) k_main(const float* __restrict__ amps,
                                              float* __restrict__ out) {
    const int b = blockIdx.y;
    const int n0 = blockIdx.x * 256;
    const int t = threadIdx.x;                   // 0..127
    const int nA = n0 + t;
    const int nB = n0 + t + 128;

    float posF = __fmul_rn((float)n0, interp_c());
    const int i0f = (int)floorf(posF);

    __shared__ u64 sA0[2][32];
    __shared__ u64 sDF[2][32];
    if (t < 64) {
        int g = t >> 5;
        int s = t & 31;
        int r0 = min(i0f + g, FRAMES - 1);
        int r1 = min(r0 + 1, FRAMES - 1);
        const u64* rowA = (const u64*)(amps + ((size_t)b * FRAMES + r0) * NH);
        const u64* rowB = (const u64*)(amps + ((size_t)b * FRAMES + r1) * NH);
        u64 a0 = __ldg(rowA + s);
        u64 a1 = __ldg(rowB + s);
        sA0[g][s] = a0;
        sDF[g][s] = sub2(a1, a0);
    }

    const float TWO_PI_F = 6.283185307179586f;
    float phA = __fmul_rn(recon_S(b, nA), TWO_PI_F);
    float phB = __fmul_rn(recon_S(b, nB), TWO_PI_F);

    float posA = __fmul_rn((float)nA, interp_c());
    float fA   = floorf(posA);
    int   iA   = (int)fA;
    float wA   = __fadd_rn(posA, -fA);
    const int gA = iA - i0f;

    float posB = __fmul_rn((float)nB, interp_c());
    float fB   = floorf(posB);
    int   iB   = (int)fB;
    float wB   = __fadd_rn(posB, -fB);
    const int gB = iB - i0f;

    __syncthreads();

    const float INV2PI = (float)(1.0 / 6.283185307179586);
    const float C1 = 6.283185482025146484375f;
    const float C2 = -1.7484556e-7f;
    const float MAGIC = 12582912.0f;             // 1.5 * 2^23

    u64 wA2 = pk(wA, wA);
    u64 wB2 = pk(wB, wB);
    u64 pA2 = pk(phA, phA);
    u64 pB2 = pk(phB, phB);
    u64 IV2 = pk(INV2PI, INV2PI);
    u64 MG2 = pk(MAGIC, MAGIC);
    u64 C1n = pk(-C1, -C1);
    u64 C2n = pk(-C2, -C2);
    u64 accA0 = pk(0.0f, 0.0f), accA1 = pk(0.0f, 0.0f);
    u64 accB0 = pk(0.0f, 0.0f), accB1 = pk(0.0f, 0.0f);

    #pragma unroll
    for (int q = 0; q < NH / 4; ++q) {
        u64 h0 = pk((float)(4 * q + 1), (float)(4 * q + 2));
        u64 h1 = pk((float)(4 * q + 3), (float)(4 * q + 4));

        u64 ampA0 = fma2(wA2, sDF[gA][2 * q],     sA0[gA][2 * q]);
        u64 ampA1 = fma2(wA2, sDF[gA][2 * q + 1], sA0[gA][2 * q + 1]);
        u64 ampB0 = fma2(wB2, sDF[gB][2 * q],     sA0[gB][2 * q]);
        u64 ampB1 = fma2(wB2, sDF[gB][2 * q + 1], sA0[gB][2 * q + 1]);

        {   u64 pr = mul2(pA2, h0);
            u64 tt = fma2(pr, IV2, MG2);
            u64 kf = sub2(tt, MG2);
            u64 r  = fma2(kf, C1n, pr);
            r      = fma2(kf, C2n, r);
            float rl, rh; upk(r, rl, rh);
            accA0  = fma2(pk(__sinf(rl), __sinf(rh)), ampA0, accA0);
        }
        {   u64 pr = mul2(pB2, h0);
            u64 tt = fma2(pr, IV2, MG2);
            u64 kf = sub2(tt, MG2);
            u64 r  = fma2(kf, C1n, pr);
            r      = fma2(kf, C2n, r);
            float rl, rh; upk(r, rl, rh);
            accB0  = fma2(pk(__sinf(rl), __sinf(rh)), ampB0, accB0);
        }
        {   u64 pr = mul2(pA2, h1);
            u64 tt = fma2(pr, IV2, MG2);
            u64 kf = sub2(tt, MG2);
            u64 r  = fma2(kf, C1n, pr);
            r      = fma2(kf, C2n, r);
            float rl, rh; upk(r, rl, rh);
            accA1  = fma2(pk(__sinf(rl), __sinf(rh)), ampA1, accA1);
        }
        {   u64 pr = mul2(pB2, h1);
            u64 tt = fma2(pr, IV2, MG2);
            u64 kf = sub2(tt, MG2);
            u64 r  = fma2(kf, C1n, pr);
            r      = fma2(kf, C2n, r);
            float rl, rh; upk(r, rl, rh);
            accB1  = fma2(pk(__sinf(rl), __sinf(rh)), ampB1, accB1);
        }
    }
    float a0l, a0h, a1l, a1h, b0l, b0h, b1l, b1h;
    upk(accA0, a0l, a0h); upk(accA1, a1l, a1h);
    upk(accB0, b0l, b0h); upk(accB1, b1l, b1h);
    out[(size_t)b * NS + nA] = (a0l + a0h) + (a1l + a1h);
    out[(size_t)b * NS + nB] = (b0l + b0h) + (b1l + b1h);
}

extern "C" void kernel_launch(void* const* d_in, const int* in_sizes, int n_in,
                              void* d_out, int out_size) {
    const float* f0   = (const float*)d_in[0];   // (8, 512)
    const float* amps = (const float*)d_in[1];   // (8, 512, 64)
    float* out = (float*)d_out;                  // (8, 262144)

    k1<<<dim3(ROWS / 256, BATCH), 256>>>(f0);
    k2<<<BATCH, 128>>>();
    k_main<<<dim3(NS / 256, BATCH), 128>>>(amps, out);
}